// round 5
// baseline (speedup 1.0000x reference)
#include <cuda_runtime.h>
#include <cuda_bf16.h>
#include <math.h>

// Problem constants (fixed by the dataset)
#define N_NODES 100000
#define E_EDGES 1600000
#define IN_C    128
#define HID_C   128
#define OUT_C   64

#define SCAN_B   512                 // elements per scan block
#define SCAN_NB  ((N_NODES + SCAN_B) / SCAN_B + 1)   // 197 blocks covers N+1 elems

// ---------------------------------------------------------------------------
// Scratch: __device__ globals (sanctioned; no allocation APIs anywhere)
// ---------------------------------------------------------------------------
__device__ int   g_is64;                  // 1 if edge_index is int64, 0 if int32
__device__ int   g_rowptr[N_NODES + 1];   // CSR row pointers (by dst)
__device__ int   g_cur   [N_NODES];       // fill cursors
__device__ int   g_csrc  [E_EDGES];       // CSR column (src) indices
__device__ int   g_bsum  [SCAN_NB];       // scan block sums
__device__ float g_dinv  [N_NODES];
__device__ float g_h     [(size_t)N_NODES * 128];  // GEMM output of current layer
__device__ float g_a     [(size_t)N_NODES * 128];  // aggregated output / next input

// ---------------------------------------------------------------------------
// edge_index dtype detection + safe accessor.
// If int64 (values < 2^31), the hi 32-bit word of every element is 0.
// ---------------------------------------------------------------------------
__global__ void detect_dtype_kernel(const int* __restrict__ ei32) {
    if (threadIdx.x == 0 && blockIdx.x == 0) {
        int is64 = 1;
        #pragma unroll
        for (int i = 0; i < 32; ++i) {
            if (ei32[2 * i + 1] != 0) { is64 = 0; break; }
        }
        g_is64 = is64;
    }
}

__device__ __forceinline__ int edge_val(const void* __restrict__ ei, long long idx) {
    if (g_is64) return (int)((const long long*)ei)[idx];
    return ((const int*)ei)[idx];
}

// ---------------------------------------------------------------------------
// CSR construction (int atomics only, in two small kernels)
// ---------------------------------------------------------------------------
__global__ void zero_rowptr_kernel() {
    int i = blockIdx.x * blockDim.x + threadIdx.x;
    if (i <= N_NODES) g_rowptr[i] = 0;
}

__global__ void hist_kernel(const void* __restrict__ ei) {
    int e = blockIdx.x * blockDim.x + threadIdx.x;
    if (e < E_EDGES) {
        int d = edge_val(ei, (long long)E_EDGES + e);   // edge_index[1, e]
        atomicAdd(&g_rowptr[d + 1], 1);
    }
}

// Inclusive scan, stage 1: per-block scan of 512 elements + block sums
__global__ void scan_block_kernel() {
    __shared__ int s[SCAN_B];
    const int t   = threadIdx.x;
    const int idx = blockIdx.x * SCAN_B + t;
    int v = (idx <= N_NODES) ? g_rowptr[idx] : 0;
    s[t] = v;
    __syncthreads();
    #pragma unroll
    for (int off = 1; off < SCAN_B; off <<= 1) {
        int add = (t >= off) ? s[t - off] : 0;
        __syncthreads();
        s[t] += add;
        __syncthreads();
    }
    if (idx <= N_NODES) g_rowptr[idx] = s[t];
    if (t == SCAN_B - 1) g_bsum[blockIdx.x] = s[t];
}

// Stage 2: single block scans the block sums (inclusive)
__global__ void scan_bsums_kernel() {
    __shared__ int s[256];
    const int t = threadIdx.x;   // 256 threads, SCAN_NB <= 256
    int v = (t < SCAN_NB) ? g_bsum[t] : 0;
    s[t] = v;
    __syncthreads();
    #pragma unroll
    for (int off = 1; off < 256; off <<= 1) {
        int add = (t >= off) ? s[t - off] : 0;
        __syncthreads();
        s[t] += add;
        __syncthreads();
    }
    if (t < SCAN_NB) g_bsum[t] = s[t];
}

// Stage 3: add preceding-block offsets; also init cursors
__global__ void scan_finish_kernel() {
    const int idx = blockIdx.x * blockDim.x + threadIdx.x;
    if (idx > N_NODES) return;
    const int b = idx / SCAN_B;
    int v = g_rowptr[idx];
    if (b > 0) v += g_bsum[b - 1];
    g_rowptr[idx] = v;
    if (idx < N_NODES) g_cur[idx] = v;   // exclusive start of row idx
}

__global__ void dinv_kernel() {
    int v = blockIdx.x * blockDim.x + threadIdx.x;
    if (v < N_NODES) {
        int deg = g_rowptr[v + 1] - g_rowptr[v] + 1;   // + self loop
        g_dinv[v] = rsqrtf((float)deg);
    }
}

__global__ void fill_csr_kernel(const void* __restrict__ ei) {
    int e = blockIdx.x * blockDim.x + threadIdx.x;
    if (e < E_EDGES) {
        int s = edge_val(ei, e);
        int d = edge_val(ei, (long long)E_EDGES + e);
        int pos = atomicAdd(&g_cur[d], 1);
        g_csrc[pos] = s;
    }
}

// ---------------------------------------------------------------------------
// GEMM: g_h[r, :] = f(X[r, :]) @ W,  K = 128 fixed, W is [K, COLS] row-major.
// If Xin == nullptr, input is read from g_a.
// If PRERELU: f(x_k) = max(x_k + bprev_k, 0).
// ---------------------------------------------------------------------------
template<int COLS, bool PRERELU>
__global__ void __launch_bounds__(512)
gemm_kernel(const float* __restrict__ Xin,
            const float* __restrict__ W,
            const float* __restrict__ bprev) {
    constexpr int K   = 128;
    constexpr int KT  = (COLS == 128) ? 32 : 128;   // K-tile size
    constexpr int NT  = K / KT;                     // number of K tiles
    constexpr int CPT = COLS / 32;                  // cols per thread (4 or 2)
    constexpr int TY  = 16;                         // rows in flight (512/32)
    constexpr int RPB = 64;                         // rows per block

    __shared__ float Ws[KT * COLS];
    __shared__ float xs[TY][KT];

    const float* X = Xin ? Xin : g_a;
    const int lane = threadIdx.x & 31;
    const int ty   = threadIdx.x >> 5;
    const int row0 = blockIdx.x * RPB;

    for (int rr = 0; rr < RPB; rr += TY) {
        const int r = row0 + rr + ty;
        float acc[CPT];
        #pragma unroll
        for (int c = 0; c < CPT; ++c) acc[c] = 0.0f;

        #pragma unroll
        for (int kt = 0; kt < NT; ++kt) {
            const int k0 = kt * KT;

            if (NT > 1 || rr == 0) {
                for (int i = threadIdx.x; i < KT * COLS; i += 512)
                    Ws[i] = W[k0 * COLS + i];
            }
            for (int i = threadIdx.x; i < TY * KT; i += 512) {
                const int ty2 = i / KT;
                const int k   = i % KT;
                const int r2  = row0 + rr + ty2;
                float v = 0.0f;
                if (r2 < N_NODES) {
                    v = X[(size_t)r2 * K + k0 + k];
                    if (PRERELU) v = fmaxf(v + bprev[k0 + k], 0.0f);
                }
                xs[ty2][k] = v;
            }
            __syncthreads();

            if (r < N_NODES) {
                #pragma unroll 8
                for (int k = 0; k < KT; ++k) {
                    const float xv = xs[ty][k];
                    #pragma unroll
                    for (int c = 0; c < CPT; ++c)
                        acc[c] = fmaf(xv, Ws[k * COLS + lane + 32 * c], acc[c]);
                }
            }
            __syncthreads();
        }

        if (r < N_NODES) {
            #pragma unroll
            for (int c = 0; c < CPT; ++c)
                g_h[(size_t)r * COLS + lane + 32 * c] = acc[c];
        }
    }
}

// ---------------------------------------------------------------------------
// CSR gather aggregation (NO atomics), vectorized:
//   g_a[v, :] = dinv[v] * ( dinv[v]*g_h[v, :] + sum_{s in row(v)} dinv[s]*g_h[s, :] )
// One warp per node. COLS=128 -> one float4/lane; COLS=64 -> one float2/lane.
// ---------------------------------------------------------------------------
__global__ void agg_gather128_kernel() {
    const int v    = blockIdx.x * (blockDim.x >> 5) + (threadIdx.x >> 5);
    const int lane = threadIdx.x & 31;
    if (v >= N_NODES) return;

    const int   r0 = g_rowptr[v];
    const int   r1 = g_rowptr[v + 1];
    const float dv = g_dinv[v];

    const float4* H = reinterpret_cast<const float4*>(g_h);
    float4*       A = reinterpret_cast<float4*>(g_a);

    float4 t = H[(size_t)v * 32 + lane];
    float4 acc = make_float4(dv * t.x, dv * t.y, dv * t.z, dv * t.w);

    for (int j = r0; j < r1; ++j) {
        const int   s  = g_csrc[j];       // warp-uniform broadcast load
        const float ws = g_dinv[s];
        float4 hv = H[(size_t)s * 32 + lane];
        acc.x = fmaf(ws, hv.x, acc.x);
        acc.y = fmaf(ws, hv.y, acc.y);
        acc.z = fmaf(ws, hv.z, acc.z);
        acc.w = fmaf(ws, hv.w, acc.w);
    }

    acc.x *= dv; acc.y *= dv; acc.z *= dv; acc.w *= dv;
    A[(size_t)v * 32 + lane] = acc;
}

__global__ void agg_gather64_kernel() {
    const int v    = blockIdx.x * (blockDim.x >> 5) + (threadIdx.x >> 5);
    const int lane = threadIdx.x & 31;
    if (v >= N_NODES) return;

    const int   r0 = g_rowptr[v];
    const int   r1 = g_rowptr[v + 1];
    const float dv = g_dinv[v];

    const float2* H = reinterpret_cast<const float2*>(g_h);
    float2*       A = reinterpret_cast<float2*>(g_a);

    float2 t = H[(size_t)v * 32 + lane];
    float2 acc = make_float2(dv * t.x, dv * t.y);

    for (int j = r0; j < r1; ++j) {
        const int   s  = g_csrc[j];
        const float ws = g_dinv[s];
        float2 hv = H[(size_t)s * 32 + lane];
        acc.x = fmaf(ws, hv.x, acc.x);
        acc.y = fmaf(ws, hv.y, acc.y);
    }

    acc.x *= dv; acc.y *= dv;
    A[(size_t)v * 32 + lane] = acc;
}

// ---------------------------------------------------------------------------
// Final: out = log_softmax(g_a + b3) over 64 columns. One warp per row.
// ---------------------------------------------------------------------------
__global__ void logsoftmax_kernel(const float* __restrict__ b,
                                  float* __restrict__ out) {
    const int row  = blockIdx.x * (blockDim.x >> 5) + (threadIdx.x >> 5);
    const int lane = threadIdx.x & 31;
    if (row >= N_NODES) return;

    const size_t base = (size_t)row * OUT_C;
    float v0 = g_a[base + lane]      + b[lane];
    float v1 = g_a[base + 32 + lane] + b[lane + 32];

    float m = fmaxf(v0, v1);
    #pragma unroll
    for (int o = 16; o; o >>= 1) m = fmaxf(m, __shfl_xor_sync(0xffffffffu, m, o));
    float s = expf(v0 - m) + expf(v1 - m);
    #pragma unroll
    for (int o = 16; o; o >>= 1) s += __shfl_xor_sync(0xffffffffu, s, o);
    const float lse = m + logf(s);

    out[base + lane]      = v0 - lse;
    out[base + 32 + lane] = v1 - lse;
}

// ---------------------------------------------------------------------------
// Launcher (graph-capturable: kernel launches only)
// ---------------------------------------------------------------------------
extern "C" void kernel_launch(void* const* d_in, const int* in_sizes, int n_in,
                              void* d_out, int out_size) {
    const float* x  = (const float*)d_in[0];
    const void*  ei = d_in[1];                  // int32 or int64 (detected on device)
    const float* W1 = (const float*)d_in[2];
    const float* b1 = (const float*)d_in[3];
    const float* W2 = (const float*)d_in[4];
    const float* b2 = (const float*)d_in[5];
    const float* W3 = (const float*)d_in[6];
    const float* b3 = (const float*)d_in[7];
    float* out = (float*)d_out;

    const int nb_nodes = (N_NODES + 256) / 256;          // covers N+1
    const int nb_edges = (E_EDGES + 255) / 256;

    // --- dtype detect + CSR build (dst-grouped) + dinv ---
    detect_dtype_kernel<<<1, 32>>>((const int*)ei);
    zero_rowptr_kernel<<<nb_nodes, 256>>>();
    hist_kernel<<<nb_edges, 256>>>(ei);
    scan_block_kernel<<<SCAN_NB, SCAN_B>>>();
    scan_bsums_kernel<<<1, 256>>>();
    scan_finish_kernel<<<nb_nodes, 256>>>();
    dinv_kernel<<<nb_nodes, 256>>>();
    fill_csr_kernel<<<nb_edges, 256>>>(ei);

    const int gemm_blocks   = (N_NODES + 63) / 64;
    const int gather_blocks = (N_NODES * 32 + 255) / 256;

    // --- Layer 1: h = x @ W1 ; a = Ahat h  (bias+relu fused into next GEMM) ---
    gemm_kernel<HID_C, false><<<gemm_blocks, 512>>>(x, W1, nullptr);
    agg_gather128_kernel<<<gather_blocks, 256>>>();

    // --- Layer 2: h = relu(a + b1) @ W2 ; aggregate ---
    gemm_kernel<HID_C, true><<<gemm_blocks, 512>>>(nullptr, W2, b1);
    agg_gather128_kernel<<<gather_blocks, 256>>>();

    // --- Layer 3: h = relu(a + b2) @ W3 (64 cols) ; aggregate ---
    gemm_kernel<OUT_C, true><<<gemm_blocks, 512>>>(nullptr, W3, b2);
    agg_gather64_kernel<<<gather_blocks, 256>>>();

    // --- log_softmax(a + b3) ---
    logsoftmax_kernel<<<(N_NODES * 32 + 255) / 256, 256>>>(b3, out);
}

// round 6
// speedup vs baseline: 1.7507x; 1.7507x over previous
#include <cuda_runtime.h>
#include <cuda_bf16.h>
#include <math.h>

// Problem constants (fixed by the dataset)
#define N_NODES 100000
#define E_EDGES 1600000
#define IN_C    128
#define HID_C   128
#define OUT_C   64

#define SCAN_B   512
#define SCAN_NB  ((N_NODES + SCAN_B) / SCAN_B + 1)

typedef unsigned long long ull;

// ---------------------------------------------------------------------------
// Scratch: __device__ globals
// ---------------------------------------------------------------------------
__device__ int   g_is64;
__device__ int   g_rowptr[N_NODES + 1];
__device__ int   g_cur   [N_NODES];
__device__ int   g_csrc  [E_EDGES];
__device__ int   g_bsum  [SCAN_NB];
__device__ float g_dinv  [N_NODES];
__device__ float g_h     [(size_t)N_NODES * 128];
__device__ float g_a     [(size_t)N_NODES * 128];

// ---------------------------------------------------------------------------
// Packed fp32x2 FMA (Blackwell dual fp32 pipe; only reachable via PTX)
// d = a * b + c, lanewise on packed {lo,hi} floats
// ---------------------------------------------------------------------------
__device__ __forceinline__ ull fma2(ull a, ull b, ull c) {
    ull d;
    asm("fma.rn.f32x2 %0, %1, %2, %3;" : "=l"(d) : "l"(a), "l"(b), "l"(c));
    return d;
}

// ---------------------------------------------------------------------------
// edge_index dtype detection (JAX may deliver int32 despite int64 in source)
// ---------------------------------------------------------------------------
__global__ void detect_dtype_kernel(const int* __restrict__ ei32) {
    if (threadIdx.x == 0 && blockIdx.x == 0) {
        int is64 = 1;
        #pragma unroll
        for (int i = 0; i < 32; ++i) {
            if (ei32[2 * i + 1] != 0) { is64 = 0; break; }
        }
        g_is64 = is64;
    }
}

__device__ __forceinline__ int edge_val(const void* __restrict__ ei, long long idx) {
    if (g_is64) return (int)((const long long*)ei)[idx];
    return ((const int*)ei)[idx];
}

// ---------------------------------------------------------------------------
// CSR construction
// ---------------------------------------------------------------------------
__global__ void zero_rowptr_kernel() {
    int i = blockIdx.x * blockDim.x + threadIdx.x;
    if (i <= N_NODES) g_rowptr[i] = 0;
}

__global__ void hist_kernel(const void* __restrict__ ei) {
    int e = blockIdx.x * blockDim.x + threadIdx.x;
    if (e < E_EDGES) {
        int d = edge_val(ei, (long long)E_EDGES + e);
        atomicAdd(&g_rowptr[d + 1], 1);
    }
}

__global__ void scan_block_kernel() {
    __shared__ int s[SCAN_B];
    const int t   = threadIdx.x;
    const int idx = blockIdx.x * SCAN_B + t;
    int v = (idx <= N_NODES) ? g_rowptr[idx] : 0;
    s[t] = v;
    __syncthreads();
    #pragma unroll
    for (int off = 1; off < SCAN_B; off <<= 1) {
        int add = (t >= off) ? s[t - off] : 0;
        __syncthreads();
        s[t] += add;
        __syncthreads();
    }
    if (idx <= N_NODES) g_rowptr[idx] = s[t];
    if (t == SCAN_B - 1) g_bsum[blockIdx.x] = s[t];
}

__global__ void scan_bsums_kernel() {
    __shared__ int s[256];
    const int t = threadIdx.x;
    int v = (t < SCAN_NB) ? g_bsum[t] : 0;
    s[t] = v;
    __syncthreads();
    #pragma unroll
    for (int off = 1; off < 256; off <<= 1) {
        int add = (t >= off) ? s[t - off] : 0;
        __syncthreads();
        s[t] += add;
        __syncthreads();
    }
    if (t < SCAN_NB) g_bsum[t] = s[t];
}

__global__ void scan_finish_kernel() {
    const int idx = blockIdx.x * blockDim.x + threadIdx.x;
    if (idx > N_NODES) return;
    const int b = idx / SCAN_B;
    int v = g_rowptr[idx];
    if (b > 0) v += g_bsum[b - 1];
    g_rowptr[idx] = v;
    if (idx < N_NODES) g_cur[idx] = v;
}

__global__ void dinv_kernel() {
    int v = blockIdx.x * blockDim.x + threadIdx.x;
    if (v < N_NODES) {
        int deg = g_rowptr[v + 1] - g_rowptr[v] + 1;
        g_dinv[v] = rsqrtf((float)deg);
    }
}

__global__ void fill_csr_kernel(const void* __restrict__ ei) {
    int e = blockIdx.x * blockDim.x + threadIdx.x;
    if (e < E_EDGES) {
        int s = edge_val(ei, e);
        int d = edge_val(ei, (long long)E_EDGES + e);
        int pos = atomicAdd(&g_cur[d], 1);
        g_csrc[pos] = s;
    }
}

// ---------------------------------------------------------------------------
// Register-tiled GEMM with packed f32x2 FMAs.
//   g_h[r, :] = f(X[r, :]) @ W,  K = 128, W row-major [K, COLS].
// Block tile: 64 rows x COLS. Thread micro-tile: 8 rows x 4 cols.
// Threads = (COLS/4) * 8.  W read as ulonglong2 (2 col-pairs);
// x stored duplicated {x,x} in smem so fma2 operand is a direct LDS.64.
// ---------------------------------------------------------------------------
template<int COLS, bool PRERELU>
__global__ void __launch_bounds__(256)
gemm_kernel(const float* __restrict__ Xin,
            const float* __restrict__ W,
            const float* __restrict__ bprev) {
    constexpr int K   = 128;
    constexpr int KT  = 32;
    constexpr int NT  = K / KT;
    constexpr int G   = COLS / 4;       // col groups (32 or 16)
    constexpr int RPB = 64;
    const int nT = G * 8;               // block threads (256 or 128)

    __shared__ float  Ws[KT * COLS];
    __shared__ float2 xsd[KT][RPB + 1]; // padded to de-conflict writes

    const float* X = Xin ? Xin : g_a;
    const int t   = threadIdx.x;
    const int cx  = t % G;              // col group -> cols [4cx, 4cx+4)
    const int ry  = t / G;              // row group -> rows [8ry, 8ry+8)
    const int row0 = blockIdx.x * RPB;

    ull acc[8][2];
    #pragma unroll
    for (int r = 0; r < 8; ++r) { acc[r][0] = 0ull; acc[r][1] = 0ull; }

    #pragma unroll 1
    for (int kt = 0; kt < NT; ++kt) {
        const int k0 = kt * KT;

        // W tile: KT*COLS floats, coalesced float4 loads
        const float4* Wg = reinterpret_cast<const float4*>(W + k0 * COLS);
        for (int i = t; i < KT * COLS / 4; i += nT)
            reinterpret_cast<float4*>(Ws)[i] = Wg[i];

        // X tile: RPB rows x KT k, coalesced reads (k fastest), duplicated store
        for (int i = t; i < RPB * KT; i += nT) {
            const int kk  = i & (KT - 1);
            const int row = i / KT;
            const int r2  = row0 + row;
            float v = 0.0f;
            if (r2 < N_NODES) {
                v = X[(size_t)r2 * K + k0 + kk];
                if (PRERELU) v = fmaxf(v + bprev[k0 + kk], 0.0f);
            }
            xsd[kk][row] = make_float2(v, v);
        }
        __syncthreads();

        #pragma unroll 8
        for (int kk = 0; kk < KT; ++kk) {
            const ulonglong2 wp =
                *reinterpret_cast<const ulonglong2*>(&Ws[kk * COLS + 4 * cx]);
            #pragma unroll
            for (int r = 0; r < 8; ++r) {
                const ull xp = *reinterpret_cast<const ull*>(&xsd[kk][ry * 8 + r]);
                acc[r][0] = fma2(xp, wp.x, acc[r][0]);
                acc[r][1] = fma2(xp, wp.y, acc[r][1]);
            }
        }
        __syncthreads();
    }

    #pragma unroll
    for (int r = 0; r < 8; ++r) {
        const int row = row0 + ry * 8 + r;
        if (row < N_NODES) {
            *reinterpret_cast<ulonglong2*>(&g_h[(size_t)row * COLS + 4 * cx]) =
                make_ulonglong2(acc[r][0], acc[r][1]);
        }
    }
}

// ---------------------------------------------------------------------------
// CSR gather aggregation (no atomics), 128 cols, warp per node, float4/lane,
// 2-wide unrolled neighbor loop for MLP.
// ---------------------------------------------------------------------------
__global__ void agg_gather128_kernel() {
    const int v    = blockIdx.x * (blockDim.x >> 5) + (threadIdx.x >> 5);
    const int lane = threadIdx.x & 31;
    if (v >= N_NODES) return;

    const int   r0 = g_rowptr[v];
    const int   r1 = g_rowptr[v + 1];
    const float dv = g_dinv[v];

    const float4* H = reinterpret_cast<const float4*>(g_h);
    float4*       A = reinterpret_cast<float4*>(g_a);

    float4 t = H[(size_t)v * 32 + lane];
    float4 acc = make_float4(dv * t.x, dv * t.y, dv * t.z, dv * t.w);

    int j = r0;
    for (; j + 1 < r1; j += 2) {
        const int   s0 = g_csrc[j];
        const int   s1 = g_csrc[j + 1];
        const float w0 = g_dinv[s0];
        const float w1 = g_dinv[s1];
        const float4 h0 = H[(size_t)s0 * 32 + lane];
        const float4 h1 = H[(size_t)s1 * 32 + lane];
        acc.x = fmaf(w0, h0.x, fmaf(w1, h1.x, acc.x));
        acc.y = fmaf(w0, h0.y, fmaf(w1, h1.y, acc.y));
        acc.z = fmaf(w0, h0.z, fmaf(w1, h1.z, acc.z));
        acc.w = fmaf(w0, h0.w, fmaf(w1, h1.w, acc.w));
    }
    if (j < r1) {
        const int   s  = g_csrc[j];
        const float ws = g_dinv[s];
        const float4 hv = H[(size_t)s * 32 + lane];
        acc.x = fmaf(ws, hv.x, acc.x);
        acc.y = fmaf(ws, hv.y, acc.y);
        acc.z = fmaf(ws, hv.z, acc.z);
        acc.w = fmaf(ws, hv.w, acc.w);
    }

    acc.x *= dv; acc.y *= dv; acc.z *= dv; acc.w *= dv;
    A[(size_t)v * 32 + lane] = acc;
}

// ---------------------------------------------------------------------------
// Layer 3 fused: gather(64 cols) + bias + log_softmax -> out.
// 16 lanes per node, float4 per lane (cols 4hl..4hl+3).
// ---------------------------------------------------------------------------
__global__ void agg64_softmax_kernel(const float* __restrict__ b,
                                     float* __restrict__ out) {
    const int gid  = blockIdx.x * blockDim.x + threadIdx.x;
    const int v    = gid >> 4;
    const int hl   = threadIdx.x & 15;
    if (v >= N_NODES) return;

    const int   r0 = g_rowptr[v];
    const int   r1 = g_rowptr[v + 1];
    const float dv = g_dinv[v];

    const float4* H = reinterpret_cast<const float4*>(g_h);

    float4 t = H[(size_t)v * 16 + hl];
    float4 acc = make_float4(dv * t.x, dv * t.y, dv * t.z, dv * t.w);

    int j = r0;
    for (; j + 1 < r1; j += 2) {
        const int   s0 = g_csrc[j];
        const int   s1 = g_csrc[j + 1];
        const float w0 = g_dinv[s0];
        const float w1 = g_dinv[s1];
        const float4 h0 = H[(size_t)s0 * 16 + hl];
        const float4 h1 = H[(size_t)s1 * 16 + hl];
        acc.x = fmaf(w0, h0.x, fmaf(w1, h1.x, acc.x));
        acc.y = fmaf(w0, h0.y, fmaf(w1, h1.y, acc.y));
        acc.z = fmaf(w0, h0.z, fmaf(w1, h1.z, acc.z));
        acc.w = fmaf(w0, h0.w, fmaf(w1, h1.w, acc.w));
    }
    if (j < r1) {
        const int   s  = g_csrc[j];
        const float ws = g_dinv[s];
        const float4 hv = H[(size_t)s * 16 + hl];
        acc.x = fmaf(ws, hv.x, acc.x);
        acc.y = fmaf(ws, hv.y, acc.y);
        acc.z = fmaf(ws, hv.z, acc.z);
        acc.w = fmaf(ws, hv.w, acc.w);
    }

    const float4 bb = reinterpret_cast<const float4*>(b)[hl];
    float4 val;
    val.x = acc.x * dv + bb.x;
    val.y = acc.y * dv + bb.y;
    val.z = acc.z * dv + bb.z;
    val.w = acc.w * dv + bb.w;

    // log_softmax over the 64 values held by this 16-lane group
    float m = fmaxf(fmaxf(val.x, val.y), fmaxf(val.z, val.w));
    #pragma unroll
    for (int o = 8; o; o >>= 1) m = fmaxf(m, __shfl_xor_sync(0xffffffffu, m, o));
    float s = expf(val.x - m) + expf(val.y - m) + expf(val.z - m) + expf(val.w - m);
    #pragma unroll
    for (int o = 8; o; o >>= 1) s += __shfl_xor_sync(0xffffffffu, s, o);
    const float lse = m + logf(s);

    float4 o4;
    o4.x = val.x - lse; o4.y = val.y - lse; o4.z = val.z - lse; o4.w = val.w - lse;
    reinterpret_cast<float4*>(out)[(size_t)v * 16 + hl] = o4;
}

// ---------------------------------------------------------------------------
// Launcher (graph-capturable: kernel launches only)
// ---------------------------------------------------------------------------
extern "C" void kernel_launch(void* const* d_in, const int* in_sizes, int n_in,
                              void* d_out, int out_size) {
    const float* x  = (const float*)d_in[0];
    const void*  ei = d_in[1];
    const float* W1 = (const float*)d_in[2];
    const float* b1 = (const float*)d_in[3];
    const float* W2 = (const float*)d_in[4];
    const float* b2 = (const float*)d_in[5];
    const float* W3 = (const float*)d_in[6];
    const float* b3 = (const float*)d_in[7];
    float* out = (float*)d_out;

    const int nb_nodes = (N_NODES + 256) / 256;   // covers N+1
    const int nb_edges = (E_EDGES + 255) / 256;

    // --- dtype detect + CSR build (dst-grouped) + dinv ---
    detect_dtype_kernel<<<1, 32>>>((const int*)ei);
    zero_rowptr_kernel<<<nb_nodes, 256>>>();
    hist_kernel<<<nb_edges, 256>>>(ei);
    scan_block_kernel<<<SCAN_NB, SCAN_B>>>();
    scan_bsums_kernel<<<1, 256>>>();
    scan_finish_kernel<<<nb_nodes, 256>>>();
    dinv_kernel<<<nb_nodes, 256>>>();
    fill_csr_kernel<<<nb_edges, 256>>>(ei);

    const int gemm_blocks   = (N_NODES + 63) / 64;
    const int gather_blocks = (N_NODES * 32 + 255) / 256;   // warp per node
    const int fused_blocks  = (N_NODES * 16 + 255) / 256;   // 16 lanes per node

    // --- Layer 1: h = x @ W1 ; a = Ahat h ---
    gemm_kernel<HID_C, false><<<gemm_blocks, 256>>>(x, W1, nullptr);
    agg_gather128_kernel<<<gather_blocks, 256>>>();

    // --- Layer 2: h = relu(a + b1) @ W2 ; a = Ahat h ---
    gemm_kernel<HID_C, true><<<gemm_blocks, 256>>>(nullptr, W2, b1);
    agg_gather128_kernel<<<gather_blocks, 256>>>();

    // --- Layer 3: h = relu(a + b2) @ W3 ; out = log_softmax(Ahat h + b3) ---
    gemm_kernel<OUT_C, true><<<gemm_blocks, 128>>>(nullptr, W3, b2);
    agg64_softmax_kernel<<<fused_blocks, 256>>>(b3, out);
}

// round 7
// speedup vs baseline: 2.1684x; 1.2386x over previous
#include <cuda_runtime.h>
#include <cuda_bf16.h>
#include <math.h>

// Problem constants (fixed by the dataset)
#define N_NODES 100000
#define E_EDGES 1600000
#define IN_C    128
#define HID_C   128
#define OUT_C   64

#define SCAN_B   512
#define SCAN_NB  ((N_NODES + SCAN_B) / SCAN_B + 1)

typedef unsigned int uint;

// ---------------------------------------------------------------------------
// Scratch: __device__ globals
// ---------------------------------------------------------------------------
__device__ int   g_is64;
__device__ int   g_rowptr[N_NODES + 1];
__device__ int   g_cur   [N_NODES];
__device__ int   g_csrc  [E_EDGES];
__device__ int   g_bsum  [SCAN_NB];
__device__ float g_dinv  [N_NODES];
__device__ float g_h     [(size_t)N_NODES * 128];
__device__ float g_a     [(size_t)N_NODES * 128];

// ---------------------------------------------------------------------------
// tf32 helpers
// ---------------------------------------------------------------------------
__device__ __forceinline__ float to_tf32(float x) {
    float y;
    asm("cvt.rna.tf32.f32 %0, %1;" : "=f"(y) : "f"(x));
    return y;
}

__device__ __forceinline__ void mma_tf32(float c[4],
                                         uint a0, uint a1, uint a2, uint a3,
                                         uint b0, uint b1) {
    asm volatile(
        "mma.sync.aligned.m16n8k8.row.col.f32.tf32.tf32.f32 "
        "{%0,%1,%2,%3}, {%4,%5,%6,%7}, {%8,%9}, {%0,%1,%2,%3};"
        : "+f"(c[0]), "+f"(c[1]), "+f"(c[2]), "+f"(c[3])
        : "r"(a0), "r"(a1), "r"(a2), "r"(a3), "r"(b0), "r"(b1));
}

// ---------------------------------------------------------------------------
// edge_index dtype detection (JAX may deliver int32 despite int64 in source)
// ---------------------------------------------------------------------------
__global__ void detect_dtype_kernel(const int* __restrict__ ei32) {
    if (threadIdx.x == 0 && blockIdx.x == 0) {
        int is64 = 1;
        #pragma unroll
        for (int i = 0; i < 32; ++i) {
            if (ei32[2 * i + 1] != 0) { is64 = 0; break; }
        }
        g_is64 = is64;
    }
}

__device__ __forceinline__ int edge_val(const void* __restrict__ ei, long long idx) {
    if (g_is64) return (int)((const long long*)ei)[idx];
    return ((const int*)ei)[idx];
}

// ---------------------------------------------------------------------------
// CSR construction
// ---------------------------------------------------------------------------
__global__ void zero_rowptr_kernel() {
    int i = blockIdx.x * blockDim.x + threadIdx.x;
    if (i <= N_NODES) g_rowptr[i] = 0;
}

__global__ void hist_kernel(const void* __restrict__ ei) {
    int e = blockIdx.x * blockDim.x + threadIdx.x;
    if (e < E_EDGES) {
        int d = edge_val(ei, (long long)E_EDGES + e);
        atomicAdd(&g_rowptr[d + 1], 1);
    }
}

// dinv can be computed from raw counts (before the scan): deg = count + 1
__global__ void dinv_kernel() {
    int v = blockIdx.x * blockDim.x + threadIdx.x;
    if (v < N_NODES) g_dinv[v] = rsqrtf((float)(g_rowptr[v + 1] + 1));
}

__global__ void scan_block_kernel() {
    __shared__ int s[SCAN_B];
    const int t   = threadIdx.x;
    const int idx = blockIdx.x * SCAN_B + t;
    int v = (idx <= N_NODES) ? g_rowptr[idx] : 0;
    s[t] = v;
    __syncthreads();
    #pragma unroll
    for (int off = 1; off < SCAN_B; off <<= 1) {
        int add = (t >= off) ? s[t - off] : 0;
        __syncthreads();
        s[t] += add;
        __syncthreads();
    }
    if (idx <= N_NODES) g_rowptr[idx] = s[t];
    if (t == SCAN_B - 1) g_bsum[blockIdx.x] = s[t];
}

__global__ void scan_bsums_kernel() {
    __shared__ int s[256];
    const int t = threadIdx.x;
    int v = (t < SCAN_NB) ? g_bsum[t] : 0;
    s[t] = v;
    __syncthreads();
    #pragma unroll
    for (int off = 1; off < 256; off <<= 1) {
        int add = (t >= off) ? s[t - off] : 0;
        __syncthreads();
        s[t] += add;
        __syncthreads();
    }
    if (t < SCAN_NB) g_bsum[t] = s[t];
}

__global__ void scan_finish_kernel() {
    const int idx = blockIdx.x * blockDim.x + threadIdx.x;
    if (idx > N_NODES) return;
    const int b = idx / SCAN_B;
    int v = g_rowptr[idx];
    if (b > 0) v += g_bsum[b - 1];
    g_rowptr[idx] = v;
    if (idx < N_NODES) g_cur[idx] = v;
}

__global__ void fill_csr_kernel(const void* __restrict__ ei) {
    int e = blockIdx.x * blockDim.x + threadIdx.x;
    if (e < E_EDGES) {
        int s = edge_val(ei, e);
        int d = edge_val(ei, (long long)E_EDGES + e);
        int pos = atomicAdd(&g_cur[d], 1);
        g_csrc[pos] = s;
    }
}

// ---------------------------------------------------------------------------
// Tensor-core GEMM (tf32 HMMA):  g_h[r, :] = f(X[r, :]) @ W
//   K = 128, W row-major [K, COLS].  Block tile: 128 rows x COLS, 8 warps
//   laid out 4(M) x 2(N); warp tile 32 x (COLS/2); m16n8k8 fragments.
//   X/W staged through smem in 32-k chunks, converted to tf32 at staging.
// ---------------------------------------------------------------------------
template<int COLS, bool PRERELU>
__global__ void __launch_bounds__(256)
gemm_tc_kernel(const float* __restrict__ Xin,
               const float* __restrict__ W,
               const float* __restrict__ bprev) {
    constexpr int K    = 128;
    constexpr int KT   = 32;            // k-chunk
    constexpr int ROWS = 128;           // block rows
    constexpr int WN   = COLS / 2;      // warp cols (64 or 32)
    constexpr int MT   = 2;             // m16 tiles per warp (32 rows)
    constexpr int NT   = WN / 8;        // n8 tiles per warp (8 or 4)
    constexpr int XPAD = 4;             // xs stride 36 -> A-frag LDS conflict-free
    constexpr int WPAD = 4;

    __shared__ float xs[ROWS][KT + XPAD];
    __shared__ float ws[KT][COLS + WPAD];

    const float* X = Xin ? Xin : g_a;
    const int t    = threadIdx.x;
    const int lane = t & 31;
    const int w    = t >> 5;
    const int wm   = w & 3;             // 0..3 (M)
    const int wn   = w >> 2;            // 0..1 (N)
    const int g    = lane >> 2;         // groupID 0..7
    const int tig  = lane & 3;          // thread-in-group 0..3
    const int row0 = blockIdx.x * ROWS;

    float acc[MT][NT][4];
    #pragma unroll
    for (int m = 0; m < MT; ++m)
        #pragma unroll
        for (int n = 0; n < NT; ++n)
            #pragma unroll
            for (int i = 0; i < 4; ++i) acc[m][n][i] = 0.0f;

    #pragma unroll 1
    for (int kc = 0; kc < K; kc += KT) {
        // Stage W chunk [KT x COLS], coalesced (n fastest), cvt to tf32
        for (int i = t; i < KT * COLS; i += 256) {
            const int k = i / COLS;
            const int n = i % COLS;
            ws[k][n] = to_tf32(W[(kc + k) * COLS + n]);
        }
        // Stage X chunk [ROWS x KT], coalesced (k fastest), bias+relu fused
        for (int i = t; i < ROWS * KT; i += 256) {
            const int r = i >> 5;        // / KT
            const int k = i & (KT - 1);
            const int rr = row0 + r;
            float v = 0.0f;
            if (rr < N_NODES) {
                v = X[(size_t)rr * K + kc + k];
                if (PRERELU) v = fmaxf(v + bprev[kc + k], 0.0f);
            }
            xs[r][k] = to_tf32(v);
        }
        __syncthreads();

        #pragma unroll
        for (int ks = 0; ks < KT / 8; ++ks) {
            const int kb = ks * 8;
            // A fragments for both m-tiles
            uint a[MT][4];
            #pragma unroll
            for (int m = 0; m < MT; ++m) {
                const int ar = wm * 32 + m * 16;
                a[m][0] = __float_as_uint(xs[ar + g    ][kb + tig    ]);
                a[m][1] = __float_as_uint(xs[ar + g + 8][kb + tig    ]);
                a[m][2] = __float_as_uint(xs[ar + g    ][kb + tig + 4]);
                a[m][3] = __float_as_uint(xs[ar + g + 8][kb + tig + 4]);
            }
            #pragma unroll
            for (int n = 0; n < NT; ++n) {
                const int nc = wn * WN + n * 8 + g;
                const uint b0 = __float_as_uint(ws[kb + tig    ][nc]);
                const uint b1 = __float_as_uint(ws[kb + tig + 4][nc]);
                #pragma unroll
                for (int m = 0; m < MT; ++m)
                    mma_tf32(acc[m][n], a[m][0], a[m][1], a[m][2], a[m][3], b0, b1);
            }
        }
        __syncthreads();
    }

    // Epilogue: c0/c1 -> (row, 2*tig), c2/c3 -> (row+8, 2*tig)
    #pragma unroll
    for (int m = 0; m < MT; ++m) {
        const int r0 = row0 + wm * 32 + m * 16 + g;
        #pragma unroll
        for (int n = 0; n < NT; ++n) {
            const int col = wn * WN + n * 8 + 2 * tig;
            if (r0 < N_NODES)
                *reinterpret_cast<float2*>(&g_h[(size_t)r0 * COLS + col]) =
                    make_float2(acc[m][n][0], acc[m][n][1]);
            if (r0 + 8 < N_NODES)
                *reinterpret_cast<float2*>(&g_h[(size_t)(r0 + 8) * COLS + col]) =
                    make_float2(acc[m][n][2], acc[m][n][3]);
        }
    }
}

// ---------------------------------------------------------------------------
// CSR gather aggregation (no atomics), 128 cols, warp per node, float4/lane
// ---------------------------------------------------------------------------
__global__ void agg_gather128_kernel() {
    const int v    = blockIdx.x * (blockDim.x >> 5) + (threadIdx.x >> 5);
    const int lane = threadIdx.x & 31;
    if (v >= N_NODES) return;

    const int   r0 = g_rowptr[v];
    const int   r1 = g_rowptr[v + 1];
    const float dv = g_dinv[v];

    const float4* H = reinterpret_cast<const float4*>(g_h);
    float4*       A = reinterpret_cast<float4*>(g_a);

    float4 t = H[(size_t)v * 32 + lane];
    float4 acc = make_float4(dv * t.x, dv * t.y, dv * t.z, dv * t.w);

    int j = r0;
    for (; j + 1 < r1; j += 2) {
        const int   s0 = g_csrc[j];
        const int   s1 = g_csrc[j + 1];
        const float w0 = g_dinv[s0];
        const float w1 = g_dinv[s1];
        const float4 h0 = H[(size_t)s0 * 32 + lane];
        const float4 h1 = H[(size_t)s1 * 32 + lane];
        acc.x = fmaf(w0, h0.x, fmaf(w1, h1.x, acc.x));
        acc.y = fmaf(w0, h0.y, fmaf(w1, h1.y, acc.y));
        acc.z = fmaf(w0, h0.z, fmaf(w1, h1.z, acc.z));
        acc.w = fmaf(w0, h0.w, fmaf(w1, h1.w, acc.w));
    }
    if (j < r1) {
        const int   s  = g_csrc[j];
        const float ws = g_dinv[s];
        const float4 hv = H[(size_t)s * 32 + lane];
        acc.x = fmaf(ws, hv.x, acc.x);
        acc.y = fmaf(ws, hv.y, acc.y);
        acc.z = fmaf(ws, hv.z, acc.z);
        acc.w = fmaf(ws, hv.w, acc.w);
    }

    acc.x *= dv; acc.y *= dv; acc.z *= dv; acc.w *= dv;
    A[(size_t)v * 32 + lane] = acc;
}

// ---------------------------------------------------------------------------
// Layer 3 fused: gather(64 cols) + bias + log_softmax -> out.
// 16 lanes per node, float4 per lane.
// ---------------------------------------------------------------------------
__global__ void agg64_softmax_kernel(const float* __restrict__ b,
                                     float* __restrict__ out) {
    const int gid  = blockIdx.x * blockDim.x + threadIdx.x;
    const int v    = gid >> 4;
    const int hl   = threadIdx.x & 15;
    if (v >= N_NODES) return;

    const int   r0 = g_rowptr[v];
    const int   r1 = g_rowptr[v + 1];
    const float dv = g_dinv[v];

    const float4* H = reinterpret_cast<const float4*>(g_h);

    float4 t = H[(size_t)v * 16 + hl];
    float4 acc = make_float4(dv * t.x, dv * t.y, dv * t.z, dv * t.w);

    int j = r0;
    for (; j + 1 < r1; j += 2) {
        const int   s0 = g_csrc[j];
        const int   s1 = g_csrc[j + 1];
        const float w0 = g_dinv[s0];
        const float w1 = g_dinv[s1];
        const float4 h0 = H[(size_t)s0 * 16 + hl];
        const float4 h1 = H[(size_t)s1 * 16 + hl];
        acc.x = fmaf(w0, h0.x, fmaf(w1, h1.x, acc.x));
        acc.y = fmaf(w0, h0.y, fmaf(w1, h1.y, acc.y));
        acc.z = fmaf(w0, h0.z, fmaf(w1, h1.z, acc.z));
        acc.w = fmaf(w0, h0.w, fmaf(w1, h1.w, acc.w));
    }
    if (j < r1) {
        const int   s  = g_csrc[j];
        const float ws = g_dinv[s];
        const float4 hv = H[(size_t)s * 16 + hl];
        acc.x = fmaf(ws, hv.x, acc.x);
        acc.y = fmaf(ws, hv.y, acc.y);
        acc.z = fmaf(ws, hv.z, acc.z);
        acc.w = fmaf(ws, hv.w, acc.w);
    }

    const float4 bb = reinterpret_cast<const float4*>(b)[hl];
    float4 val;
    val.x = acc.x * dv + bb.x;
    val.y = acc.y * dv + bb.y;
    val.z = acc.z * dv + bb.z;
    val.w = acc.w * dv + bb.w;

    float m = fmaxf(fmaxf(val.x, val.y), fmaxf(val.z, val.w));
    #pragma unroll
    for (int o = 8; o; o >>= 1) m = fmaxf(m, __shfl_xor_sync(0xffffffffu, m, o));
    float s = expf(val.x - m) + expf(val.y - m) + expf(val.z - m) + expf(val.w - m);
    #pragma unroll
    for (int o = 8; o; o >>= 1) s += __shfl_xor_sync(0xffffffffu, s, o);
    const float lse = m + logf(s);

    float4 o4;
    o4.x = val.x - lse; o4.y = val.y - lse; o4.z = val.z - lse; o4.w = val.w - lse;
    reinterpret_cast<float4*>(out)[(size_t)v * 16 + hl] = o4;
}

// ---------------------------------------------------------------------------
// Launcher (graph-capturable: kernel launches only)
// ---------------------------------------------------------------------------
extern "C" void kernel_launch(void* const* d_in, const int* in_sizes, int n_in,
                              void* d_out, int out_size) {
    const float* x  = (const float*)d_in[0];
    const void*  ei = d_in[1];
    const float* W1 = (const float*)d_in[2];
    const float* b1 = (const float*)d_in[3];
    const float* W2 = (const float*)d_in[4];
    const float* b2 = (const float*)d_in[5];
    const float* W3 = (const float*)d_in[6];
    const float* b3 = (const float*)d_in[7];
    float* out = (float*)d_out;

    const int nb_nodes = (N_NODES + 256) / 256;
    const int nb_edges = (E_EDGES + 255) / 256;

    // --- dtype detect + CSR build (dst-grouped) + dinv ---
    detect_dtype_kernel<<<1, 32>>>((const int*)ei);
    zero_rowptr_kernel<<<nb_nodes, 256>>>();
    hist_kernel<<<nb_edges, 256>>>(ei);
    dinv_kernel<<<nb_nodes, 256>>>();        // from raw counts (deg = count + 1)
    scan_block_kernel<<<SCAN_NB, SCAN_B>>>();
    scan_bsums_kernel<<<1, 256>>>();
    scan_finish_kernel<<<nb_nodes, 256>>>();
    fill_csr_kernel<<<nb_edges, 256>>>(ei);

    const int gemm_blocks   = (N_NODES + 127) / 128;
    const int gather_blocks = (N_NODES * 32 + 255) / 256;
    const int fused_blocks  = (N_NODES * 16 + 255) / 256;

    // --- Layer 1 ---
    gemm_tc_kernel<HID_C, false><<<gemm_blocks, 256>>>(x, W1, nullptr);
    agg_gather128_kernel<<<gather_blocks, 256>>>();

    // --- Layer 2 ---
    gemm_tc_kernel<HID_C, true><<<gemm_blocks, 256>>>(nullptr, W2, b1);
    agg_gather128_kernel<<<gather_blocks, 256>>>();

    // --- Layer 3 + fused softmax ---
    gemm_tc_kernel<OUT_C, true><<<gemm_blocks, 256>>>(nullptr, W3, b2);
    agg64_softmax_kernel<<<fused_blocks, 256>>>(b3, out);
}

// round 8
// speedup vs baseline: 2.3663x; 1.0913x over previous
#include <cuda_runtime.h>
#include <cuda_bf16.h>
#include <math.h>

// Problem constants (fixed by the dataset)
#define N_NODES 100000
#define E_EDGES 1600000
#define IN_C    128
#define HID_C   128
#define OUT_C   64

#define SCAN_B   512
#define SCAN_NB  ((N_NODES + SCAN_B) / SCAN_B + 1)

typedef unsigned int uint;

// ---------------------------------------------------------------------------
// Scratch: __device__ globals
// ---------------------------------------------------------------------------
__device__ int   g_is64;
__device__ int   g_rowptr[N_NODES + 1];
__device__ int   g_cur   [N_NODES];
__device__ int   g_csrc  [E_EDGES];
__device__ int   g_bsum  [SCAN_NB];
__device__ float g_dinv  [N_NODES];
__device__ float g_h     [(size_t)N_NODES * 128];
__device__ float g_a     [(size_t)N_NODES * 128];

// ---------------------------------------------------------------------------
// tf32 helpers
// ---------------------------------------------------------------------------
__device__ __forceinline__ float to_tf32(float x) {
    float y;
    asm("cvt.rna.tf32.f32 %0, %1;" : "=f"(y) : "f"(x));
    return y;
}

__device__ __forceinline__ void mma_tf32(float c[4],
                                         uint a0, uint a1, uint a2, uint a3,
                                         uint b0, uint b1) {
    asm volatile(
        "mma.sync.aligned.m16n8k8.row.col.f32.tf32.tf32.f32 "
        "{%0,%1,%2,%3}, {%4,%5,%6,%7}, {%8,%9}, {%0,%1,%2,%3};"
        : "+f"(c[0]), "+f"(c[1]), "+f"(c[2]), "+f"(c[3])
        : "r"(a0), "r"(a1), "r"(a2), "r"(a3), "r"(b0), "r"(b1));
}

__device__ __forceinline__ int edge_val(const void* __restrict__ ei, long long idx) {
    if (g_is64) return (int)((const long long*)ei)[idx];
    return ((const int*)ei)[idx];
}

// ---------------------------------------------------------------------------
// Setup: zero rowptr + parallel dtype detect (warp ballot, block 0)
// ---------------------------------------------------------------------------
__global__ void setup_kernel(const int* __restrict__ ei32) {
    int i = blockIdx.x * blockDim.x + threadIdx.x;
    if (i <= N_NODES) g_rowptr[i] = 0;
    if (blockIdx.x == 0 && threadIdx.x < 32) {
        // int64 edge values < 2^31 -> every odd 32-bit word is zero
        int nz = (ei32[2 * threadIdx.x + 1] != 0) ? 1 : 0;
        uint any_nz = __ballot_sync(0xffffffffu, nz);
        if (threadIdx.x == 0) g_is64 = (any_nz == 0u) ? 1 : 0;
    }
}

__global__ void hist_kernel(const void* __restrict__ ei) {
    int e = blockIdx.x * blockDim.x + threadIdx.x;
    if (e < E_EDGES) {
        int d = edge_val(ei, (long long)E_EDGES + e);
        atomicAdd(&g_rowptr[d + 1], 1);
    }
}

// Per-block inclusive scan; also computes dinv from the raw count it loads.
__global__ void scan_block_kernel() {
    __shared__ int s[SCAN_B];
    const int t   = threadIdx.x;
    const int idx = blockIdx.x * SCAN_B + t;
    int v = (idx <= N_NODES) ? g_rowptr[idx] : 0;
    // raw count at rowptr[n+1] belongs to node n; deg = count + 1 (self loop)
    if (idx >= 1 && idx <= N_NODES) g_dinv[idx - 1] = rsqrtf((float)(v + 1));
    s[t] = v;
    __syncthreads();
    #pragma unroll
    for (int off = 1; off < SCAN_B; off <<= 1) {
        int add = (t >= off) ? s[t - off] : 0;
        __syncthreads();
        s[t] += add;
        __syncthreads();
    }
    if (idx <= N_NODES) g_rowptr[idx] = s[t];
    if (t == SCAN_B - 1) g_bsum[blockIdx.x] = s[t];
}

__global__ void scan_bsums_kernel() {
    __shared__ int s[256];
    const int t = threadIdx.x;
    int v = (t < SCAN_NB) ? g_bsum[t] : 0;
    s[t] = v;
    __syncthreads();
    #pragma unroll
    for (int off = 1; off < 256; off <<= 1) {
        int add = (t >= off) ? s[t - off] : 0;
        __syncthreads();
        s[t] += add;
        __syncthreads();
    }
    if (t < SCAN_NB) g_bsum[t] = s[t];
}

__global__ void scan_finish_kernel() {
    const int idx = blockIdx.x * blockDim.x + threadIdx.x;
    if (idx > N_NODES) return;
    const int b = idx / SCAN_B;
    int v = g_rowptr[idx];
    if (b > 0) v += g_bsum[b - 1];
    g_rowptr[idx] = v;
    if (idx < N_NODES) g_cur[idx] = v;
}

__global__ void fill_csr_kernel(const void* __restrict__ ei) {
    int e = blockIdx.x * blockDim.x + threadIdx.x;
    if (e < E_EDGES) {
        int s = edge_val(ei, e);
        int d = edge_val(ei, (long long)E_EDGES + e);
        int pos = atomicAdd(&g_cur[d], 1);
        g_csrc[pos] = s;
    }
}

// ---------------------------------------------------------------------------
// Tensor-core GEMM (tf32 HMMA):  g_h[r, :] = f(X[r, :]) @ W
// ---------------------------------------------------------------------------
template<int COLS, bool PRERELU>
__global__ void __launch_bounds__(256)
gemm_tc_kernel(const float* __restrict__ Xin,
               const float* __restrict__ W,
               const float* __restrict__ bprev) {
    constexpr int K    = 128;
    constexpr int KT   = 32;
    constexpr int ROWS = 128;
    constexpr int WN   = COLS / 2;
    constexpr int MT   = 2;
    constexpr int NT   = WN / 8;
    constexpr int XPAD = 4;
    constexpr int WPAD = 4;

    __shared__ float xs[ROWS][KT + XPAD];
    __shared__ float ws[KT][COLS + WPAD];

    const float* X = Xin ? Xin : g_a;
    const int t    = threadIdx.x;
    const int lane = t & 31;
    const int w    = t >> 5;
    const int wm   = w & 3;
    const int wn   = w >> 2;
    const int g    = lane >> 2;
    const int tig  = lane & 3;
    const int row0 = blockIdx.x * ROWS;

    float acc[MT][NT][4];
    #pragma unroll
    for (int m = 0; m < MT; ++m)
        #pragma unroll
        for (int n = 0; n < NT; ++n)
            #pragma unroll
            for (int i = 0; i < 4; ++i) acc[m][n][i] = 0.0f;

    #pragma unroll 1
    for (int kc = 0; kc < K; kc += KT) {
        for (int i = t; i < KT * COLS; i += 256) {
            const int k = i / COLS;
            const int n = i % COLS;
            ws[k][n] = to_tf32(W[(kc + k) * COLS + n]);
        }
        for (int i = t; i < ROWS * KT; i += 256) {
            const int r = i >> 5;
            const int k = i & (KT - 1);
            const int rr = row0 + r;
            float v = 0.0f;
            if (rr < N_NODES) {
                v = X[(size_t)rr * K + kc + k];
                if (PRERELU) v = fmaxf(v + bprev[kc + k], 0.0f);
            }
            xs[r][k] = to_tf32(v);
        }
        __syncthreads();

        #pragma unroll
        for (int ks = 0; ks < KT / 8; ++ks) {
            const int kb = ks * 8;
            uint a[MT][4];
            #pragma unroll
            for (int m = 0; m < MT; ++m) {
                const int ar = wm * 32 + m * 16;
                a[m][0] = __float_as_uint(xs[ar + g    ][kb + tig    ]);
                a[m][1] = __float_as_uint(xs[ar + g + 8][kb + tig    ]);
                a[m][2] = __float_as_uint(xs[ar + g    ][kb + tig + 4]);
                a[m][3] = __float_as_uint(xs[ar + g + 8][kb + tig + 4]);
            }
            #pragma unroll
            for (int n = 0; n < NT; ++n) {
                const int nc = wn * WN + n * 8 + g;
                const uint b0 = __float_as_uint(ws[kb + tig    ][nc]);
                const uint b1 = __float_as_uint(ws[kb + tig + 4][nc]);
                #pragma unroll
                for (int m = 0; m < MT; ++m)
                    mma_tf32(acc[m][n], a[m][0], a[m][1], a[m][2], a[m][3], b0, b1);
            }
        }
        __syncthreads();
    }

    #pragma unroll
    for (int m = 0; m < MT; ++m) {
        const int r0 = row0 + wm * 32 + m * 16 + g;
        #pragma unroll
        for (int n = 0; n < NT; ++n) {
            const int col = wn * WN + n * 8 + 2 * tig;
            if (r0 < N_NODES)
                *reinterpret_cast<float2*>(&g_h[(size_t)r0 * COLS + col]) =
                    make_float2(acc[m][n][0], acc[m][n][1]);
            if (r0 + 8 < N_NODES)
                *reinterpret_cast<float2*>(&g_h[(size_t)(r0 + 8) * COLS + col]) =
                    make_float2(acc[m][n][2], acc[m][n][3]);
        }
    }
}

// ---------------------------------------------------------------------------
// CSR gather aggregation (no atomics), 128 cols, warp/node, 4-wide unroll
// ---------------------------------------------------------------------------
__global__ void agg_gather128_kernel() {
    const int v    = blockIdx.x * (blockDim.x >> 5) + (threadIdx.x >> 5);
    const int lane = threadIdx.x & 31;
    if (v >= N_NODES) return;

    const int   r0 = g_rowptr[v];
    const int   r1 = g_rowptr[v + 1];
    const float dv = g_dinv[v];

    const float4* H = reinterpret_cast<const float4*>(g_h);
    float4*       A = reinterpret_cast<float4*>(g_a);

    float4 t = H[(size_t)v * 32 + lane];
    float4 acc = make_float4(dv * t.x, dv * t.y, dv * t.z, dv * t.w);

    int j = r0;
    for (; j + 3 < r1; j += 4) {
        const int s0 = g_csrc[j];
        const int s1 = g_csrc[j + 1];
        const int s2 = g_csrc[j + 2];
        const int s3 = g_csrc[j + 3];
        const float w0 = g_dinv[s0];
        const float w1 = g_dinv[s1];
        const float w2 = g_dinv[s2];
        const float w3 = g_dinv[s3];
        const float4 h0 = H[(size_t)s0 * 32 + lane];
        const float4 h1 = H[(size_t)s1 * 32 + lane];
        const float4 h2 = H[(size_t)s2 * 32 + lane];
        const float4 h3 = H[(size_t)s3 * 32 + lane];
        acc.x = fmaf(w0, h0.x, fmaf(w1, h1.x, fmaf(w2, h2.x, fmaf(w3, h3.x, acc.x))));
        acc.y = fmaf(w0, h0.y, fmaf(w1, h1.y, fmaf(w2, h2.y, fmaf(w3, h3.y, acc.y))));
        acc.z = fmaf(w0, h0.z, fmaf(w1, h1.z, fmaf(w2, h2.z, fmaf(w3, h3.z, acc.z))));
        acc.w = fmaf(w0, h0.w, fmaf(w1, h1.w, fmaf(w2, h2.w, fmaf(w3, h3.w, acc.w))));
    }
    for (; j < r1; ++j) {
        const int   s  = g_csrc[j];
        const float ws = g_dinv[s];
        const float4 hv = H[(size_t)s * 32 + lane];
        acc.x = fmaf(ws, hv.x, acc.x);
        acc.y = fmaf(ws, hv.y, acc.y);
        acc.z = fmaf(ws, hv.z, acc.z);
        acc.w = fmaf(ws, hv.w, acc.w);
    }

    acc.x *= dv; acc.y *= dv; acc.z *= dv; acc.w *= dv;
    A[(size_t)v * 32 + lane] = acc;
}

// ---------------------------------------------------------------------------
// Layer 3 fused: gather(64 cols) + bias + log_softmax -> out. 16 lanes/node.
// ---------------------------------------------------------------------------
__global__ void agg64_softmax_kernel(const float* __restrict__ b,
                                     float* __restrict__ out) {
    const int gid  = blockIdx.x * blockDim.x + threadIdx.x;
    const int v    = gid >> 4;
    const int hl   = threadIdx.x & 15;
    if (v >= N_NODES) return;

    const int   r0 = g_rowptr[v];
    const int   r1 = g_rowptr[v + 1];
    const float dv = g_dinv[v];

    const float4* H = reinterpret_cast<const float4*>(g_h);

    float4 t = H[(size_t)v * 16 + hl];
    float4 acc = make_float4(dv * t.x, dv * t.y, dv * t.z, dv * t.w);

    int j = r0;
    for (; j + 3 < r1; j += 4) {
        const int s0 = g_csrc[j];
        const int s1 = g_csrc[j + 1];
        const int s2 = g_csrc[j + 2];
        const int s3 = g_csrc[j + 3];
        const float w0 = g_dinv[s0];
        const float w1 = g_dinv[s1];
        const float w2 = g_dinv[s2];
        const float w3 = g_dinv[s3];
        const float4 h0 = H[(size_t)s0 * 16 + hl];
        const float4 h1 = H[(size_t)s1 * 16 + hl];
        const float4 h2 = H[(size_t)s2 * 16 + hl];
        const float4 h3 = H[(size_t)s3 * 16 + hl];
        acc.x = fmaf(w0, h0.x, fmaf(w1, h1.x, fmaf(w2, h2.x, fmaf(w3, h3.x, acc.x))));
        acc.y = fmaf(w0, h0.y, fmaf(w1, h1.y, fmaf(w2, h2.y, fmaf(w3, h3.y, acc.y))));
        acc.z = fmaf(w0, h0.z, fmaf(w1, h1.z, fmaf(w2, h2.z, fmaf(w3, h3.z, acc.z))));
        acc.w = fmaf(w0, h0.w, fmaf(w1, h1.w, fmaf(w2, h2.w, fmaf(w3, h3.w, acc.w))));
    }
    for (; j < r1; ++j) {
        const int   s  = g_csrc[j];
        const float ws = g_dinv[s];
        const float4 hv = H[(size_t)s * 16 + hl];
        acc.x = fmaf(ws, hv.x, acc.x);
        acc.y = fmaf(ws, hv.y, acc.y);
        acc.z = fmaf(ws, hv.z, acc.z);
        acc.w = fmaf(ws, hv.w, acc.w);
    }

    const float4 bb = reinterpret_cast<const float4*>(b)[hl];
    float4 val;
    val.x = acc.x * dv + bb.x;
    val.y = acc.y * dv + bb.y;
    val.z = acc.z * dv + bb.z;
    val.w = acc.w * dv + bb.w;

    float m = fmaxf(fmaxf(val.x, val.y), fmaxf(val.z, val.w));
    #pragma unroll
    for (int o = 8; o; o >>= 1) m = fmaxf(m, __shfl_xor_sync(0xffffffffu, m, o));
    float s = expf(val.x - m) + expf(val.y - m) + expf(val.z - m) + expf(val.w - m);
    #pragma unroll
    for (int o = 8; o; o >>= 1) s += __shfl_xor_sync(0xffffffffu, s, o);
    const float lse = m + logf(s);

    float4 o4;
    o4.x = val.x - lse; o4.y = val.y - lse; o4.z = val.z - lse; o4.w = val.w - lse;
    reinterpret_cast<float4*>(out)[(size_t)v * 16 + hl] = o4;
}

// ---------------------------------------------------------------------------
// Launcher (graph-capturable). Fork-join: CSR chain on a side stream overlaps
// the layer-1 GEMM on the main stream; joined before the first gather.
// ---------------------------------------------------------------------------
extern "C" void kernel_launch(void* const* d_in, const int* in_sizes, int n_in,
                              void* d_out, int out_size) {
    const float* x  = (const float*)d_in[0];
    const void*  ei = d_in[1];
    const float* W1 = (const float*)d_in[2];
    const float* b1 = (const float*)d_in[3];
    const float* W2 = (const float*)d_in[4];
    const float* b2 = (const float*)d_in[5];
    const float* W3 = (const float*)d_in[6];
    const float* b3 = (const float*)d_in[7];
    float* out = (float*)d_out;

    // Host-side resources (created once; no device-memory allocation)
    static cudaStream_t s_side = nullptr;
    static cudaEvent_t  s_fork = nullptr, s_join = nullptr;
    if (s_side == nullptr) {
        cudaStreamCreateWithFlags(&s_side, cudaStreamNonBlocking);
        cudaEventCreateWithFlags(&s_fork, cudaEventDisableTiming);
        cudaEventCreateWithFlags(&s_join, cudaEventDisableTiming);
    }

    const int nb_nodes = (N_NODES + 256) / 256;   // covers N+1
    const int nb_edges = (E_EDGES + 255) / 256;

    // --- fork: CSR build (dst-grouped CSR + dinv) on side stream ---
    cudaEventRecord(s_fork, 0);
    cudaStreamWaitEvent(s_side, s_fork, 0);

    setup_kernel<<<nb_nodes, 256, 0, s_side>>>((const int*)ei);
    hist_kernel<<<nb_edges, 256, 0, s_side>>>(ei);
    scan_block_kernel<<<SCAN_NB, SCAN_B, 0, s_side>>>();
    scan_bsums_kernel<<<1, 256, 0, s_side>>>();
    scan_finish_kernel<<<nb_nodes, 256, 0, s_side>>>();
    fill_csr_kernel<<<nb_edges, 256, 0, s_side>>>(ei);
    cudaEventRecord(s_join, s_side);

    const int gemm_blocks   = (N_NODES + 127) / 128;
    const int gather_blocks = (N_NODES * 32 + 255) / 256;
    const int fused_blocks  = (N_NODES * 16 + 255) / 256;

    // --- Layer 1 GEMM overlaps the CSR build ---
    gemm_tc_kernel<HID_C, false><<<gemm_blocks, 256>>>(x, W1, nullptr);

    // --- join, then aggregate ---
    cudaStreamWaitEvent(0, s_join, 0);
    agg_gather128_kernel<<<gather_blocks, 256>>>();

    // --- Layer 2 ---
    gemm_tc_kernel<HID_C, true><<<gemm_blocks, 256>>>(nullptr, W2, b1);
    agg_gather128_kernel<<<gather_blocks, 256>>>();

    // --- Layer 3 + fused softmax ---
    gemm_tc_kernel<OUT_C, true><<<gemm_blocks, 256>>>(nullptr, W3, b2);
    agg64_softmax_kernel<<<fused_blocks, 256>>>(b3, out);
}

// round 9
// speedup vs baseline: 2.5799x; 1.0902x over previous
#include <cuda_runtime.h>
#include <cuda_fp16.h>
#include <math.h>

// Problem constants (fixed by the dataset)
#define N_NODES 100000
#define E_EDGES 1600000
#define IN_C    128
#define HID_C   128
#define OUT_C   64

#define SCAN_B   512
#define SCAN_NB  ((N_NODES + SCAN_B) / SCAN_B + 1)

typedef unsigned int uint;

// ---------------------------------------------------------------------------
// Scratch: __device__ globals
// ---------------------------------------------------------------------------
__device__ int    g_is64;
__device__ int    g_rowptr[N_NODES + 1];
__device__ int    g_cur   [N_NODES];
__device__ int    g_csrc  [E_EDGES];
__device__ int    g_bsum  [SCAN_NB];
__device__ float  g_dinv  [N_NODES];
__device__ __half g_hh    [(size_t)N_NODES * 128];  // GEMM output (fp16, gather input)
__device__ float  g_a     [(size_t)N_NODES * 128];  // aggregated output (fp32, GEMM input)

// ---------------------------------------------------------------------------
// tf32 helpers
// ---------------------------------------------------------------------------
__device__ __forceinline__ float to_tf32(float x) {
    float y;
    asm("cvt.rna.tf32.f32 %0, %1;" : "=f"(y) : "f"(x));
    return y;
}

__device__ __forceinline__ void mma_tf32(float c[4],
                                         uint a0, uint a1, uint a2, uint a3,
                                         uint b0, uint b1) {
    asm volatile(
        "mma.sync.aligned.m16n8k8.row.col.f32.tf32.tf32.f32 "
        "{%0,%1,%2,%3}, {%4,%5,%6,%7}, {%8,%9}, {%0,%1,%2,%3};"
        : "+f"(c[0]), "+f"(c[1]), "+f"(c[2]), "+f"(c[3])
        : "r"(a0), "r"(a1), "r"(a2), "r"(a3), "r"(b0), "r"(b1));
}

__device__ __forceinline__ int edge_val(const void* __restrict__ ei, long long idx) {
    if (g_is64) return (int)((const long long*)ei)[idx];
    return ((const int*)ei)[idx];
}

// Unpack 4 halves (uint2) to 4 floats
__device__ __forceinline__ float4 h4_to_f4(uint2 p) {
    const float2 lo = __half22float2(*reinterpret_cast<__half2*>(&p.x));
    const float2 hi = __half22float2(*reinterpret_cast<__half2*>(&p.y));
    return make_float4(lo.x, lo.y, hi.x, hi.y);
}

// ---------------------------------------------------------------------------
// Setup: zero rowptr + parallel dtype detect (warp ballot, block 0)
// ---------------------------------------------------------------------------
__global__ void setup_kernel(const int* __restrict__ ei32) {
    int i = blockIdx.x * blockDim.x + threadIdx.x;
    if (i <= N_NODES) g_rowptr[i] = 0;
    if (blockIdx.x == 0 && threadIdx.x < 32) {
        int nz = (ei32[2 * threadIdx.x + 1] != 0) ? 1 : 0;
        uint any_nz = __ballot_sync(0xffffffffu, nz);
        if (threadIdx.x == 0) g_is64 = (any_nz == 0u) ? 1 : 0;
    }
}

__global__ void hist_kernel(const void* __restrict__ ei) {
    int e = blockIdx.x * blockDim.x + threadIdx.x;
    if (e < E_EDGES) {
        int d = edge_val(ei, (long long)E_EDGES + e);
        atomicAdd(&g_rowptr[d + 1], 1);
    }
}

// Per-block inclusive scan; also computes dinv from the raw count it loads.
__global__ void scan_block_kernel() {
    __shared__ int s[SCAN_B];
    const int t   = threadIdx.x;
    const int idx = blockIdx.x * SCAN_B + t;
    int v = (idx <= N_NODES) ? g_rowptr[idx] : 0;
    if (idx >= 1 && idx <= N_NODES) g_dinv[idx - 1] = rsqrtf((float)(v + 1));
    s[t] = v;
    __syncthreads();
    #pragma unroll
    for (int off = 1; off < SCAN_B; off <<= 1) {
        int add = (t >= off) ? s[t - off] : 0;
        __syncthreads();
        s[t] += add;
        __syncthreads();
    }
    if (idx <= N_NODES) g_rowptr[idx] = s[t];
    if (t == SCAN_B - 1) g_bsum[blockIdx.x] = s[t];
}

__global__ void scan_bsums_kernel() {
    __shared__ int s[256];
    const int t = threadIdx.x;
    int v = (t < SCAN_NB) ? g_bsum[t] : 0;
    s[t] = v;
    __syncthreads();
    #pragma unroll
    for (int off = 1; off < 256; off <<= 1) {
        int add = (t >= off) ? s[t - off] : 0;
        __syncthreads();
        s[t] += add;
        __syncthreads();
    }
    if (t < SCAN_NB) g_bsum[t] = s[t];
}

__global__ void scan_finish_kernel() {
    const int idx = blockIdx.x * blockDim.x + threadIdx.x;
    if (idx > N_NODES) return;
    const int b = idx / SCAN_B;
    int v = g_rowptr[idx];
    if (b > 0) v += g_bsum[b - 1];
    g_rowptr[idx] = v;
    if (idx < N_NODES) g_cur[idx] = v;
}

__global__ void fill_csr_kernel(const void* __restrict__ ei) {
    int e = blockIdx.x * blockDim.x + threadIdx.x;
    if (e < E_EDGES) {
        int s = edge_val(ei, e);
        int d = edge_val(ei, (long long)E_EDGES + e);
        int pos = atomicAdd(&g_cur[d], 1);
        g_csrc[pos] = s;
    }
}

// ---------------------------------------------------------------------------
// Tensor-core GEMM (tf32 HMMA):  g_hh[r, :] = (half) f(X[r, :]) @ W
// ---------------------------------------------------------------------------
template<int COLS, bool PRERELU>
__global__ void __launch_bounds__(256)
gemm_tc_kernel(const float* __restrict__ Xin,
               const float* __restrict__ W,
               const float* __restrict__ bprev) {
    constexpr int K    = 128;
    constexpr int KT   = 32;
    constexpr int ROWS = 128;
    constexpr int WN   = COLS / 2;
    constexpr int MT   = 2;
    constexpr int NT   = WN / 8;
    constexpr int XPAD = 4;
    constexpr int WPAD = 4;

    __shared__ float xs[ROWS][KT + XPAD];
    __shared__ float ws[KT][COLS + WPAD];

    const float* X = Xin ? Xin : g_a;
    const int t    = threadIdx.x;
    const int lane = t & 31;
    const int w    = t >> 5;
    const int wm   = w & 3;
    const int wn   = w >> 2;
    const int g    = lane >> 2;
    const int tig  = lane & 3;
    const int row0 = blockIdx.x * ROWS;

    float acc[MT][NT][4];
    #pragma unroll
    for (int m = 0; m < MT; ++m)
        #pragma unroll
        for (int n = 0; n < NT; ++n)
            #pragma unroll
            for (int i = 0; i < 4; ++i) acc[m][n][i] = 0.0f;

    #pragma unroll 1
    for (int kc = 0; kc < K; kc += KT) {
        for (int i = t; i < KT * COLS; i += 256) {
            const int k = i / COLS;
            const int n = i % COLS;
            ws[k][n] = to_tf32(W[(kc + k) * COLS + n]);
        }
        for (int i = t; i < ROWS * KT; i += 256) {
            const int r = i >> 5;
            const int k = i & (KT - 1);
            const int rr = row0 + r;
            float v = 0.0f;
            if (rr < N_NODES) {
                v = X[(size_t)rr * K + kc + k];
                if (PRERELU) v = fmaxf(v + bprev[kc + k], 0.0f);
            }
            xs[r][k] = to_tf32(v);
        }
        __syncthreads();

        #pragma unroll
        for (int ks = 0; ks < KT / 8; ++ks) {
            const int kb = ks * 8;
            uint a[MT][4];
            #pragma unroll
            for (int m = 0; m < MT; ++m) {
                const int ar = wm * 32 + m * 16;
                a[m][0] = __float_as_uint(xs[ar + g    ][kb + tig    ]);
                a[m][1] = __float_as_uint(xs[ar + g + 8][kb + tig    ]);
                a[m][2] = __float_as_uint(xs[ar + g    ][kb + tig + 4]);
                a[m][3] = __float_as_uint(xs[ar + g + 8][kb + tig + 4]);
            }
            #pragma unroll
            for (int n = 0; n < NT; ++n) {
                const int nc = wn * WN + n * 8 + g;
                const uint b0 = __float_as_uint(ws[kb + tig    ][nc]);
                const uint b1 = __float_as_uint(ws[kb + tig + 4][nc]);
                #pragma unroll
                for (int m = 0; m < MT; ++m)
                    mma_tf32(acc[m][n], a[m][0], a[m][1], a[m][2], a[m][3], b0, b1);
            }
        }
        __syncthreads();
    }

    // Epilogue: fp16 pack; c0/c1 -> (row, 2*tig..+1), c2/c3 -> (row+8, ...)
    #pragma unroll
    for (int m = 0; m < MT; ++m) {
        const int r0 = row0 + wm * 32 + m * 16 + g;
        #pragma unroll
        for (int n = 0; n < NT; ++n) {
            const int col = wn * WN + n * 8 + 2 * tig;
            if (r0 < N_NODES)
                *reinterpret_cast<__half2*>(&g_hh[(size_t)r0 * COLS + col]) =
                    __floats2half2_rn(acc[m][n][0], acc[m][n][1]);
            if (r0 + 8 < N_NODES)
                *reinterpret_cast<__half2*>(&g_hh[(size_t)(r0 + 8) * COLS + col]) =
                    __floats2half2_rn(acc[m][n][2], acc[m][n][3]);
        }
    }
}

// ---------------------------------------------------------------------------
// CSR gather aggregation (no atomics), 128 cols fp16 in / fp32 out.
// Warp per node; lane covers cols [4*lane, 4*lane+4) via one uint2 (8B) load.
// ---------------------------------------------------------------------------
__global__ void agg_gather128_kernel() {
    const int v    = blockIdx.x * (blockDim.x >> 5) + (threadIdx.x >> 5);
    const int lane = threadIdx.x & 31;
    if (v >= N_NODES) return;

    const int   r0 = g_rowptr[v];
    const int   r1 = g_rowptr[v + 1];
    const float dv = g_dinv[v];

    const uint2* H = reinterpret_cast<const uint2*>(g_hh);   // 4 halves each
    float4*      A = reinterpret_cast<float4*>(g_a);

    float4 t = h4_to_f4(H[(size_t)v * 32 + lane]);
    float4 acc = make_float4(dv * t.x, dv * t.y, dv * t.z, dv * t.w);

    int j = r0;
    for (; j + 3 < r1; j += 4) {
        const int s0 = g_csrc[j];
        const int s1 = g_csrc[j + 1];
        const int s2 = g_csrc[j + 2];
        const int s3 = g_csrc[j + 3];
        const float w0 = g_dinv[s0];
        const float w1 = g_dinv[s1];
        const float w2 = g_dinv[s2];
        const float w3 = g_dinv[s3];
        const float4 h0 = h4_to_f4(H[(size_t)s0 * 32 + lane]);
        const float4 h1 = h4_to_f4(H[(size_t)s1 * 32 + lane]);
        const float4 h2 = h4_to_f4(H[(size_t)s2 * 32 + lane]);
        const float4 h3 = h4_to_f4(H[(size_t)s3 * 32 + lane]);
        acc.x = fmaf(w0, h0.x, fmaf(w1, h1.x, fmaf(w2, h2.x, fmaf(w3, h3.x, acc.x))));
        acc.y = fmaf(w0, h0.y, fmaf(w1, h1.y, fmaf(w2, h2.y, fmaf(w3, h3.y, acc.y))));
        acc.z = fmaf(w0, h0.z, fmaf(w1, h1.z, fmaf(w2, h2.z, fmaf(w3, h3.z, acc.z))));
        acc.w = fmaf(w0, h0.w, fmaf(w1, h1.w, fmaf(w2, h2.w, fmaf(w3, h3.w, acc.w))));
    }
    for (; j < r1; ++j) {
        const int   s  = g_csrc[j];
        const float ws = g_dinv[s];
        const float4 hv = h4_to_f4(H[(size_t)s * 32 + lane]);
        acc.x = fmaf(ws, hv.x, acc.x);
        acc.y = fmaf(ws, hv.y, acc.y);
        acc.z = fmaf(ws, hv.z, acc.z);
        acc.w = fmaf(ws, hv.w, acc.w);
    }

    acc.x *= dv; acc.y *= dv; acc.z *= dv; acc.w *= dv;
    A[(size_t)v * 32 + lane] = acc;
}

// ---------------------------------------------------------------------------
// Layer 3 fused: gather(64 cols fp16) + bias + log_softmax -> out (fp32).
// 16 lanes per node; lane covers cols [4*hl, 4*hl+4).
// ---------------------------------------------------------------------------
__global__ void agg64_softmax_kernel(const float* __restrict__ b,
                                     float* __restrict__ out) {
    const int gid  = blockIdx.x * blockDim.x + threadIdx.x;
    const int v    = gid >> 4;
    const int hl   = threadIdx.x & 15;
    if (v >= N_NODES) return;

    const int   r0 = g_rowptr[v];
    const int   r1 = g_rowptr[v + 1];
    const float dv = g_dinv[v];

    const uint2* H = reinterpret_cast<const uint2*>(g_hh);   // row = 16 uint2

    float4 t = h4_to_f4(H[(size_t)v * 16 + hl]);
    float4 acc = make_float4(dv * t.x, dv * t.y, dv * t.z, dv * t.w);

    int j = r0;
    for (; j + 3 < r1; j += 4) {
        const int s0 = g_csrc[j];
        const int s1 = g_csrc[j + 1];
        const int s2 = g_csrc[j + 2];
        const int s3 = g_csrc[j + 3];
        const float w0 = g_dinv[s0];
        const float w1 = g_dinv[s1];
        const float w2 = g_dinv[s2];
        const float w3 = g_dinv[s3];
        const float4 h0 = h4_to_f4(H[(size_t)s0 * 16 + hl]);
        const float4 h1 = h4_to_f4(H[(size_t)s1 * 16 + hl]);
        const float4 h2 = h4_to_f4(H[(size_t)s2 * 16 + hl]);
        const float4 h3 = h4_to_f4(H[(size_t)s3 * 16 + hl]);
        acc.x = fmaf(w0, h0.x, fmaf(w1, h1.x, fmaf(w2, h2.x, fmaf(w3, h3.x, acc.x))));
        acc.y = fmaf(w0, h0.y, fmaf(w1, h1.y, fmaf(w2, h2.y, fmaf(w3, h3.y, acc.y))));
        acc.z = fmaf(w0, h0.z, fmaf(w1, h1.z, fmaf(w2, h2.z, fmaf(w3, h3.z, acc.z))));
        acc.w = fmaf(w0, h0.w, fmaf(w1, h1.w, fmaf(w2, h2.w, fmaf(w3, h3.w, acc.w))));
    }
    for (; j < r1; ++j) {
        const int   s  = g_csrc[j];
        const float ws = g_dinv[s];
        const float4 hv = h4_to_f4(H[(size_t)s * 16 + hl]);
        acc.x = fmaf(ws, hv.x, acc.x);
        acc.y = fmaf(ws, hv.y, acc.y);
        acc.z = fmaf(ws, hv.z, acc.z);
        acc.w = fmaf(ws, hv.w, acc.w);
    }

    const float4 bb = reinterpret_cast<const float4*>(b)[hl];
    float4 val;
    val.x = acc.x * dv + bb.x;
    val.y = acc.y * dv + bb.y;
    val.z = acc.z * dv + bb.z;
    val.w = acc.w * dv + bb.w;

    float m = fmaxf(fmaxf(val.x, val.y), fmaxf(val.z, val.w));
    #pragma unroll
    for (int o = 8; o; o >>= 1) m = fmaxf(m, __shfl_xor_sync(0xffffffffu, m, o));
    float s = expf(val.x - m) + expf(val.y - m) + expf(val.z - m) + expf(val.w - m);
    #pragma unroll
    for (int o = 8; o; o >>= 1) s += __shfl_xor_sync(0xffffffffu, s, o);
    const float lse = m + logf(s);

    float4 o4;
    o4.x = val.x - lse; o4.y = val.y - lse; o4.z = val.z - lse; o4.w = val.w - lse;
    reinterpret_cast<float4*>(out)[(size_t)v * 16 + hl] = o4;
}

// ---------------------------------------------------------------------------
// Launcher (graph-capturable). Fork-join: CSR chain on a side stream overlaps
// the layer-1 GEMM on the main stream; joined before the first gather.
// ---------------------------------------------------------------------------
extern "C" void kernel_launch(void* const* d_in, const int* in_sizes, int n_in,
                              void* d_out, int out_size) {
    const float* x  = (const float*)d_in[0];
    const void*  ei = d_in[1];
    const float* W1 = (const float*)d_in[2];
    const float* b1 = (const float*)d_in[3];
    const float* W2 = (const float*)d_in[4];
    const float* b2 = (const float*)d_in[5];
    const float* W3 = (const float*)d_in[6];
    const float* b3 = (const float*)d_in[7];
    float* out = (float*)d_out;

    static cudaStream_t s_side = nullptr;
    static cudaEvent_t  s_fork = nullptr, s_join = nullptr;
    if (s_side == nullptr) {
        cudaStreamCreateWithFlags(&s_side, cudaStreamNonBlocking);
        cudaEventCreateWithFlags(&s_fork, cudaEventDisableTiming);
        cudaEventCreateWithFlags(&s_join, cudaEventDisableTiming);
    }

    const int nb_nodes = (N_NODES + 256) / 256;
    const int nb_edges = (E_EDGES + 255) / 256;

    // --- fork: CSR build on side stream ---
    cudaEventRecord(s_fork, 0);
    cudaStreamWaitEvent(s_side, s_fork, 0);

    setup_kernel<<<nb_nodes, 256, 0, s_side>>>((const int*)ei);
    hist_kernel<<<nb_edges, 256, 0, s_side>>>(ei);
    scan_block_kernel<<<SCAN_NB, SCAN_B, 0, s_side>>>();
    scan_bsums_kernel<<<1, 256, 0, s_side>>>();
    scan_finish_kernel<<<nb_nodes, 256, 0, s_side>>>();
    fill_csr_kernel<<<nb_edges, 256, 0, s_side>>>(ei);
    cudaEventRecord(s_join, s_side);

    const int gemm_blocks   = (N_NODES + 127) / 128;
    const int gather_blocks = (N_NODES * 32 + 255) / 256;
    const int fused_blocks  = (N_NODES * 16 + 255) / 256;

    // --- Layer 1 GEMM overlaps the CSR build ---
    gemm_tc_kernel<HID_C, false><<<gemm_blocks, 256>>>(x, W1, nullptr);

    // --- join, then aggregate ---
    cudaStreamWaitEvent(0, s_join, 0);
    agg_gather128_kernel<<<gather_blocks, 256>>>();

    // --- Layer 2 ---
    gemm_tc_kernel<HID_C, true><<<gemm_blocks, 256>>>(nullptr, W2, b1);
    agg_gather128_kernel<<<gather_blocks, 256>>>();

    // --- Layer 3 + fused softmax ---
    gemm_tc_kernel<OUT_C, true><<<gemm_blocks, 256>>>(nullptr, W3, b2);
    agg64_softmax_kernel<<<fused_blocks, 256>>>(b3, out);
}